// round 1
// baseline (speedup 1.0000x reference)
#include <cuda_runtime.h>
#include <math.h>

// Problem constants (fixed by the reference)
#define S      7
#define NBOX   49          // S*S
#define NCLS   20
#define DCH    30          // B*5+C
#define BSZ    4096
#define NE     (BSZ * NBOX)   // 200704
#define CHUNK  256
#define NBLK   (NE / CHUNK)   // 784

// Persistent device scratch (allocation-free rule)
__device__ unsigned char g_entry[NE];          // bit0 valid, bit1 tp, bits[3..7] class
__device__ int           g_gt[NCLS];           // GT count per class
__device__ int           g_blk[NBLK][NCLS][2]; // per-chunk counts -> exclusive bases
__device__ double        g_ap[NCLS];           // AP accumulators

__device__ __forceinline__ float sigf(float x) {
    return 1.0f / (1.0f + expf(-x));
}

__device__ __forceinline__ float iou(const float4 a, const float4 b) {
    float lx = fmaxf(a.x, b.x), ly = fmaxf(a.y, b.y);
    float rx = fminf(a.z, b.z), ry = fminf(a.w, b.w);
    float w = fmaxf(rx - lx, 0.0f), h = fmaxf(ry - ly, 0.0f);
    float inter = w * h;
    float aa = (a.z - a.x) * (a.w - a.y);
    float ab = (b.z - b.x) * (b.w - b.y);
    return inter / (aa + ab - inter);   // matches reference (no epsilon)
}

__global__ void k_reset() {
    int t = threadIdx.x;
    if (t < NCLS) { g_gt[t] = 0; g_ap[t] = 0.0; }
}

// One block per image, 64 threads. Decode -> sort -> NMS -> match -> emit entry bytes.
__global__ void k_image(const float* __restrict__ tgt, const float* __restrict__ outp) {
    const int img = blockIdx.x;
    const int tid = threadIdx.x;

    __shared__ float st[S * S * DCH];   // 1470
    __shared__ float so[S * S * DCH];
    const float* tp_ = tgt  + (size_t)img * (S * S * DCH);
    const float* op_ = outp + (size_t)img * (S * S * DCH);
    for (int i = tid; i < S * S * DCH; i += 64) { st[i] = tp_[i]; so[i] = op_[i]; }

    __shared__ float4 pbox[NBOX];  __shared__ float pconf[NBOX]; __shared__ int pcls[NBOX];
    __shared__ float4 gbox[NBOX];  __shared__ int   gcls[NBOX];  __shared__ unsigned char gval[NBOX];
    __shared__ float4 sbox[NBOX];  __shared__ float sconf[NBOX]; __shared__ int scls[NBOX];
    __shared__ unsigned long long sup[NBOX];
    __shared__ float smx[NBOX];    __shared__ int   sbest[NBOX];
    __shared__ int   hist[NCLS];

    if (tid < NCLS) hist[tid] = 0;
    __syncthreads();

    if (tid < NBOX) {
        const int ci = tid / S, cj = tid % S;
        const float* o = so + tid * DCH;
        const float* t = st + tid * DCH;
        const float gw = 448.0f / (float)S;

        // prediction: responsible box = max-conf of the 2 boxes (tie -> box 0)
        float c0 = sigf(o[4]), c1 = sigf(o[9]);
        int resp = (c1 > c0) ? 1 : 0;
        float oc = fmaxf(c0, c1);
        float x = sigf(o[resp * 5 + 0]);
        float y = sigf(o[resp * 5 + 1]);
        float w = sigf(o[resp * 5 + 2]) * 448.0f;
        float h = sigf(o[resp * 5 + 3]) * 448.0f;
        float cx = (x + (float)cj) * gw, cy = (y + (float)ci) * gw;
        pbox[tid]  = make_float4(cx - 0.5f * w, cy - 0.5f * h, cx + 0.5f * w, cy + 0.5f * h);
        pconf[tid] = oc;
        // class argmax (sigmoid monotonic -> argmax on raw, first-tie)
        int bi = 0; float bv = o[10];
        #pragma unroll
        for (int c = 1; c < NCLS; c++) { float v = o[10 + c]; if (v > bv) { bv = v; bi = c; } }
        pcls[tid] = bi;

        // ground truth
        float tx = t[0], ty = t[1];
        float tw = t[2] * 448.0f, th = t[3] * 448.0f;
        float gcx = (tx + (float)cj) * gw, gcy = (ty + (float)ci) * gw;
        gbox[tid] = make_float4(gcx - 0.5f * tw, gcy - 0.5f * th, gcx + 0.5f * tw, gcy + 0.5f * th);
        int gi = 0; float gv = t[10];
        #pragma unroll
        for (int c = 1; c < NCLS; c++) { float v = t[10 + c]; if (v > gv) { gv = v; gi = c; } }
        gcls[tid] = gi;
        gval[tid] = (t[4] > 0.5f) ? 1 : 0;
        if (gval[tid]) atomicAdd(&hist[gi], 1);
    }
    __syncthreads();

    // stable descending sort by conf: rank = #{better} (strict conf, tie -> lower index first)
    if (tid < NBOX) {
        float myc = pconf[tid];
        int r = 0;
        for (int j = 0; j < NBOX; j++) {
            float cj2 = pconf[j];
            if (cj2 > myc || (cj2 == myc && j < tid)) r++;
        }
        sbox[r] = pbox[tid]; sconf[r] = myc; scls[r] = pcls[tid];
    }
    __syncthreads();

    // suppression masks + best-GT match per sorted pred
    if (tid < NBOX) {
        float4 b = sbox[tid];
        int kc = scls[tid];
        unsigned long long m = 0ULL;
        for (int j = 0; j < NBOX; j++) {
            if (scls[j] == kc && iou(b, sbox[j]) > 0.5f) m |= (1ULL << j);
        }
        sup[tid] = m;

        float best = -1.0f; int bid = 0;
        for (int j = 0; j < NBOX; j++) {
            float v = -1.0f;
            if (gval[j] && gcls[j] == kc) v = iou(b, gbox[j]);
            if (v > best) { best = v; bid = j; }
        }
        smx[tid] = best; sbest[tid] = bid;
    }
    __syncthreads();

    // sequential greedy NMS + greedy TP assignment (49 iters, trivial)
    if (tid == 0) {
        unsigned long long suppressed = 0ULL, matched = 0ULL;
        unsigned char* eo = g_entry + (size_t)img * NBOX;
        for (int i = 0; i < NBOX; i++) {
            bool active = !((suppressed >> i) & 1ULL);
            if (active) {
                unsigned long long above = (~0ULL) << (i + 1);
                suppressed |= sup[i] & above;
            }
            bool vp  = active && (sconf[i] > 0.5f);
            bool hit = vp && (smx[i] > 0.5f) && !((matched >> sbest[i]) & 1ULL);
            if (hit) matched |= (1ULL << sbest[i]);
            eo[i] = (unsigned char)((vp ? 1 : 0) | (hit ? 2 : 0) | (scls[i] << 3));
        }
    }
    if (tid < NCLS && hist[tid]) atomicAdd(&g_gt[tid], hist[tid]);
}

// Per-chunk per-class (active, tp) counts
__global__ void k_count() {
    __shared__ int h[NCLS][2];
    int t = threadIdx.x;
    if (t < NCLS) { h[t][0] = 0; h[t][1] = 0; }
    __syncthreads();
    unsigned char e = g_entry[(size_t)blockIdx.x * CHUNK + t];
    if (e & 1) {
        atomicAdd(&h[e >> 3][0], 1);
        if (e & 2) atomicAdd(&h[e >> 3][1], 1);
    }
    __syncthreads();
    if (t < NCLS) {
        g_blk[blockIdx.x][t][0] = h[t][0];
        g_blk[blockIdx.x][t][1] = h[t][1];
    }
}

// Exclusive scan of chunk counts (40 independent serial scans of 784 values)
__global__ void k_scan() {
    int t = threadIdx.x;
    if (t >= NCLS * 2) return;
    int c = t >> 1, w = t & 1;
    int run = 0;
    for (int b = 0; b < NBLK; b++) {
        int v = g_blk[b][c][w];
        g_blk[b][c][w] = run;
        run += v;
    }
}

// AP contributions: only (valid & tp) entries contribute to the trapezoid sum
__global__ void k_ap() {
    __shared__ unsigned char se[CHUNK];
    int t = threadIdx.x;
    int gb = blockIdx.x;
    se[t] = g_entry[(size_t)gb * CHUNK + t];
    __syncthreads();
    unsigned char e = se[t];
    if ((e & 3) == 3) {
        int c = e >> 3;
        int locA = 0, locT = 0;
        for (int j = 0; j < t; j++) {
            unsigned char ej = se[j];
            if ((ej & 1) && (int)(ej >> 3) == c) { locA++; if (ej & 2) locT++; }
        }
        int k  = g_blk[gb][c][0] + locA + 1;  // rank among active of class c (1-based)
        int TP = g_blk[gb][c][1] + locT + 1;  // cumulative TP including self
        float G = (float)g_gt[c];
        float pk = (float)TP / ((float)k + 1e-6f);
        float pprev;
        long gi = (long)gb * CHUNK + t;
        if (k > 1) pprev = (float)(TP - 1) / ((float)(k - 1) + 1e-6f);
        else       pprev = (gi == 0) ? 1.0f : 0.0f;   // prepended p=1 only at flattened idx 0
        float dr = 1.0f / (G + 1e-6f);
        atomicAdd(&g_ap[c], (double)(dr * 0.5f * (pk + pprev)));
    }
}

__global__ void k_final(float* __restrict__ out) {
    if (threadIdx.x == 0) {
        double s = 0.0; int nh = 0;
        for (int c = 0; c < NCLS; c++) {
            if (g_gt[c] > 0) { s += g_ap[c]; nh++; }
        }
        double n = (double)(nh > 0 ? nh : 1);
        out[0] = (float)(s / n);
    }
}

extern "C" void kernel_launch(void* const* d_in, const int* in_sizes, int n_in,
                              void* d_out, int out_size) {
    const float* tgt  = (const float*)d_in[0];   // target  [4096,7,7,30]
    const float* outp = (const float*)d_in[1];   // output  [4096,7,7,30]
    (void)in_sizes; (void)n_in; (void)out_size;

    k_reset<<<1, 32>>>();
    k_image<<<BSZ, 64>>>(tgt, outp);
    k_count<<<NBLK, CHUNK>>>();
    k_scan<<<1, 64>>>();
    k_ap<<<NBLK, CHUNK>>>();
    k_final<<<1, 32>>>((float*)d_out);
}

// round 4
// speedup vs baseline: 1.1972x; 1.1972x over previous
#include <cuda_runtime.h>
#include <math.h>

// Problem constants (fixed by the reference)
#define S      7
#define NBOX   49          // S*S
#define NCLS   20
#define DCH    30          // B*5+C
#define BSZ    4096
#define NE     (BSZ * NBOX)   // 200704

// Persistent device scratch (allocation-free rule)
__device__ unsigned char g_entry[NE];            // bit0 valid, bit1 tp, bits[3..7] class
__device__ int           g_gt[NCLS];             // GT count per class
__device__ int           g_cnt[2][NCLS][BSZ];    // per-image counts -> exclusive bases
__device__ double        g_ap[NCLS];             // AP accumulators

__device__ __forceinline__ float sigf(float x) {
    return 1.0f / (1.0f + expf(-x));
}

__device__ __forceinline__ float iou(const float4 a, const float4 b) {
    float lx = fmaxf(a.x, b.x), ly = fmaxf(a.y, b.y);
    float rx = fminf(a.z, b.z), ry = fminf(a.w, b.w);
    float w = fmaxf(rx - lx, 0.0f), h = fmaxf(ry - ly, 0.0f);
    float inter = w * h;
    float aa = (a.z - a.x) * (a.w - a.y);
    float ab = (b.z - b.x) * (b.w - b.y);
    return inter / (aa + ab - inter);   // matches reference (no epsilon)
}

__global__ void k_reset() {
    int t = threadIdx.x;
    if (t < NCLS) { g_gt[t] = 0; g_ap[t] = 0.0; }
}

// One block per image, 64 threads. Decode -> sort -> NMS -> match -> emit entries + counts.
__global__ void k_image(const float* __restrict__ tgt, const float* __restrict__ outp) {
    const int img = blockIdx.x;
    const int tid = threadIdx.x;

    __shared__ float st[S * S * DCH];   // 1470
    __shared__ float so[S * S * DCH];
    {   // image stride = 1470 floats = 735 float2 (8B-aligned for every image)
        const float2* tp_ = (const float2*)(tgt  + (size_t)img * (S * S * DCH));
        const float2* op_ = (const float2*)(outp + (size_t)img * (S * S * DCH));
        float2* st2 = (float2*)st; float2* so2 = (float2*)so;
        for (int i = tid; i < (S * S * DCH) / 2; i += 64) { st2[i] = tp_[i]; so2[i] = op_[i]; }
    }

    __shared__ float4 pbox[NBOX];  __shared__ float pconf[NBOX]; __shared__ int pcls[NBOX];
    __shared__ float4 gbox[NBOX];  __shared__ int   gcls[NBOX];  __shared__ unsigned char gval[NBOX];
    __shared__ float4 sbox[NBOX];  __shared__ float sconf[NBOX]; __shared__ int scls[NBOX];
    __shared__ unsigned long long sup[NBOX];
    __shared__ float smx[NBOX];    __shared__ int   sbest[NBOX];
    __shared__ int   hist[NCLS];
    __shared__ unsigned char sent[NBOX];

    if (tid < NCLS) hist[tid] = 0;
    __syncthreads();

    if (tid < NBOX) {
        const int ci = tid / S, cj = tid % S;
        const float* o = so + tid * DCH;
        const float* t = st + tid * DCH;
        const float gw = 448.0f / (float)S;

        // prediction: responsible box = max-conf box (sigmoid monotonic -> compare raw)
        int resp = (o[9] > o[4]) ? 1 : 0;
        float ocraw = fmaxf(o[4], o[9]);          // raw logit: ordering & >0.5 threshold preserved
        float x = sigf(o[resp * 5 + 0]);
        float y = sigf(o[resp * 5 + 1]);
        float w = sigf(o[resp * 5 + 2]) * 448.0f;
        float h = sigf(o[resp * 5 + 3]) * 448.0f;
        float cx = (x + (float)cj) * gw, cy = (y + (float)ci) * gw;
        pbox[tid]  = make_float4(cx - 0.5f * w, cy - 0.5f * h, cx + 0.5f * w, cy + 0.5f * h);
        pconf[tid] = ocraw;
        int bi = 0; float bv = o[10];
        #pragma unroll
        for (int c = 1; c < NCLS; c++) { float v = o[10 + c]; if (v > bv) { bv = v; bi = c; } }
        pcls[tid] = bi;

        // ground truth
        float tw = t[2] * 448.0f, th = t[3] * 448.0f;
        float gcx = (t[0] + (float)cj) * gw, gcy = (t[1] + (float)ci) * gw;
        gbox[tid] = make_float4(gcx - 0.5f * tw, gcy - 0.5f * th, gcx + 0.5f * tw, gcy + 0.5f * th);
        int gi = 0; float gv = t[10];
        #pragma unroll
        for (int c = 1; c < NCLS; c++) { float v = t[10 + c]; if (v > gv) { gv = v; gi = c; } }
        gcls[tid] = gi;
        gval[tid] = (t[4] > 0.5f) ? 1 : 0;
        if (gval[tid]) atomicAdd(&hist[gi], 1);
    }
    __syncthreads();

    // stable descending sort by conf: rank = #{better} (strict, tie -> lower index first)
    if (tid < NBOX) {
        float myc = pconf[tid];
        int r = 0;
        for (int j = 0; j < NBOX; j++) {
            float cj2 = pconf[j];
            if (cj2 > myc || (cj2 == myc && j < tid)) r++;
        }
        sbox[r] = pbox[tid]; sconf[r] = myc; scls[r] = pcls[tid];
    }
    __syncthreads();

    // suppression masks + best same-class GT per sorted pred
    if (tid < NBOX) {
        float4 b = sbox[tid];
        int kc = scls[tid];
        unsigned long long m = 0ULL;
        for (int j = 0; j < NBOX; j++) {
            if (scls[j] == kc && iou(b, sbox[j]) > 0.5f) m |= (1ULL << j);
        }
        sup[tid] = m;

        float best = -1.0f; int bid = 0;
        for (int j = 0; j < NBOX; j++) {
            float v = -1.0f;
            if (gval[j] && gcls[j] == kc) v = iou(b, gbox[j]);
            if (v > best) { best = v; bid = j; }
        }
        smx[tid] = best; sbest[tid] = bid;
    }
    __syncthreads();

    // sequential greedy NMS + greedy TP assignment (49 iters, trivial)
    if (tid == 0) {
        unsigned long long suppressed = 0ULL, matched = 0ULL;
        for (int i = 0; i < NBOX; i++) {
            bool active = !((suppressed >> i) & 1ULL);
            if (active) {
                unsigned long long above = (~0ULL) << (i + 1);
                suppressed |= sup[i] & above;
            }
            bool vp  = active && (sconf[i] > 0.0f);   // raw logit > 0 <=> sigmoid > 0.5
            bool hit = vp && (smx[i] > 0.5f) && !((matched >> sbest[i]) & 1ULL);
            if (hit) matched |= (1ULL << sbest[i]);
            sent[i] = (unsigned char)((vp ? 1 : 0) | (hit ? 2 : 0) | (scls[i] << 3));
        }
    }
    __syncthreads();

    if (tid < NBOX) g_entry[(size_t)img * NBOX + tid] = sent[tid];
    if (tid < NCLS) {
        int a = 0, p = 0;
        for (int i = 0; i < NBOX; i++) {
            unsigned char e = sent[i];
            if ((e & 1) && (int)(e >> 3) == tid) { a++; if (e & 2) p++; }
        }
        g_cnt[0][tid][img] = a;
        g_cnt[1][tid][img] = p;
        if (hist[tid]) atomicAdd(&g_gt[tid], hist[tid]);
    }
}

// Parallel exclusive scan: one block per (word, class), 4096 values, 1024 thr x 4 elems
__global__ void k_scan() {
    __shared__ int wsum[32];
    int* base = &g_cnt[0][0][0] + (size_t)blockIdx.x * BSZ;
    int t = threadIdx.x, lane = t & 31, wid = t >> 5;

    int v0 = base[t * 4 + 0], v1 = base[t * 4 + 1];
    int v2 = base[t * 4 + 2], v3 = base[t * 4 + 3];
    int s = v0 + v1 + v2 + v3;

    int inc = s;
    #pragma unroll
    for (int o = 1; o < 32; o <<= 1) {
        int n = __shfl_up_sync(0xffffffffu, inc, o);
        if (lane >= o) inc += n;
    }
    if (lane == 31) wsum[wid] = inc;
    __syncthreads();
    if (wid == 0) {
        int wv = wsum[lane];
        int wi = wv;
        #pragma unroll
        for (int o = 1; o < 32; o <<= 1) {
            int n = __shfl_up_sync(0xffffffffu, wi, o);
            if (lane >= o) wi += n;
        }
        wsum[lane] = wi - wv;   // exclusive
    }
    __syncthreads();
    int ex = wsum[wid] + (inc - s);   // exclusive base for this thread's 4 elems
    base[t * 4 + 0] = ex;
    base[t * 4 + 1] = ex + v0;
    base[t * 4 + 2] = ex + v0 + v1;
    base[t * 4 + 3] = ex + v0 + v1 + v2;
}

// AP contributions: only (valid & tp) entries contribute to the trapezoid sum
__global__ void k_ap() {
    __shared__ unsigned char se[NBOX];
    int t = threadIdx.x;
    int img = blockIdx.x;
    if (t < NBOX) se[t] = g_entry[(size_t)img * NBOX + t];
    __syncthreads();
    if (t < NBOX) {
        unsigned char e = se[t];
        if ((e & 3) == 3) {
            int c = e >> 3;
            int locA = 0, locT = 0;
            for (int j = 0; j < t; j++) {
                unsigned char ej = se[j];
                if ((ej & 1) && (int)(ej >> 3) == c) { locA++; if (ej & 2) locT++; }
            }
            int k  = g_cnt[0][c][img] + locA + 1;  // rank among active of class c (1-based)
            int TP = g_cnt[1][c][img] + locT + 1;  // cumulative TP including self
            float G = (float)g_gt[c];
            float pk = (float)TP / ((float)k + 1e-6f);
            float pprev;
            if (k > 1) pprev = (float)(TP - 1) / ((float)(k - 1) + 1e-6f);
            else       pprev = ((img | t) == 0) ? 1.0f : 0.0f; // prepended p=1 only at flat idx 0
            float dr = 1.0f / (G + 1e-6f);
            atomicAdd(&g_ap[c], (double)(dr * 0.5f * (pk + pprev)));
        }
    }
}

__global__ void k_final(float* __restrict__ out) {
    if (threadIdx.x == 0) {
        double s = 0.0; int nh = 0;
        for (int c = 0; c < NCLS; c++) {
            if (g_gt[c] > 0) { s += g_ap[c]; nh++; }
        }
        double n = (double)(nh > 0 ? nh : 1);
        out[0] = (float)(s / n);
    }
}

extern "C" void kernel_launch(void* const* d_in, const int* in_sizes, int n_in,
                              void* d_out, int out_size) {
    const float* tgt  = (const float*)d_in[0];   // target  [4096,7,7,30]
    const float* outp = (const float*)d_in[1];   // output  [4096,7,7,30]
    (void)in_sizes; (void)n_in; (void)out_size;

    k_reset<<<1, 32>>>();
    k_image<<<BSZ, 64>>>(tgt, outp);
    k_scan<<<2 * NCLS, 1024>>>();
    k_ap<<<BSZ, 64>>>();
    k_final<<<1, 32>>>((float*)d_out);
}

// round 8
// speedup vs baseline: 1.4163x; 1.1830x over previous
#include <cuda_runtime.h>
#include <math.h>

// Problem constants (fixed by the reference)
#define S      7
#define NBOX   49          // S*S
#define NCLS   20
#define DCH    30          // B*5+C
#define BSZ    4096
#define NE     (BSZ * NBOX)   // 200704

// Persistent device scratch (allocation-free rule)
__device__ unsigned char      g_entry[NE];          // bit0 valid, bit1 tp, bits[3..7] class
__device__ int                g_gt[NCLS];           // GT count per class
__device__ int                g_cnt[2][NCLS][BSZ];  // per-image counts -> exclusive bases
__device__ unsigned long long g_actM[BSZ][NCLS];    // per-image per-class valid-pred bitmask
__device__ unsigned long long g_tpM[BSZ][NCLS];     // per-image per-class TP bitmask
__device__ double             g_ap[NCLS];           // AP accumulators

__device__ __forceinline__ float sigf(float x) {
    return 1.0f / (1.0f + expf(-x));
}

__device__ __forceinline__ float iou(const float4 a, const float4 b) {
    float lx = fmaxf(a.x, b.x), ly = fmaxf(a.y, b.y);
    float rx = fminf(a.z, b.z), ry = fminf(a.w, b.w);
    float w = fmaxf(rx - lx, 0.0f), h = fmaxf(ry - ly, 0.0f);
    float inter = w * h;
    float aa = (a.z - a.x) * (a.w - a.y);
    float ab = (b.z - b.x) * (b.w - b.y);
    return inter / (aa + ab - inter);   // matches reference (no epsilon)
}

__global__ void k_reset() {
    int t = threadIdx.x;
    if (t < NCLS) { g_gt[t] = 0; g_ap[t] = 0.0; }
}

// One block per image, 128 threads.
__global__ void k_image(const float* __restrict__ tgt, const float* __restrict__ outp) {
    const int img = blockIdx.x;
    const int tid = threadIdx.x;

    __shared__ float4 pbox[NBOX];  __shared__ float pconf[NBOX]; __shared__ int pcls[NBOX];
    __shared__ float4 gbox[NBOX];  __shared__ int   gcls[NBOX];  __shared__ unsigned char gval[NBOX];
    __shared__ float4 sbox[NBOX];  __shared__ float sconf[NBOX]; __shared__ int scls[NBOX];
    __shared__ unsigned long long sup[NBOX];
    __shared__ float smx[NBOX];    __shared__ int   sbest[NBOX];
    __shared__ int   hist[NCLS];
    __shared__ unsigned char sent[NBOX];
    __shared__ unsigned long long sActM[NCLS], sTpM[NCLS];

    if (tid < NCLS) { hist[tid] = 0; sActM[tid] = 0ULL; sTpM[tid] = 0ULL; }
    __syncthreads();

    // ---- decode: each of 49 threads loads its own 120B cell directly (float2 x15) ----
    if (tid < NBOX) {
        const int ci = tid / S, cj = tid % S;
        const float gw = 448.0f / (float)S;

        float o[DCH], t[DCH];
        {
            const float2* ob = (const float2*)(outp + (size_t)img * (S * S * DCH) + tid * DCH);
            const float2* tb = (const float2*)(tgt  + (size_t)img * (S * S * DCH) + tid * DCH);
            #pragma unroll
            for (int k = 0; k < DCH / 2; k++) {
                float2 v = ob[k]; o[2 * k] = v.x; o[2 * k + 1] = v.y;
                float2 u = tb[k]; t[2 * k] = u.x; t[2 * k + 1] = u.y;
            }
        }

        // prediction: responsible box = max-conf box (sigmoid monotonic -> compare raw)
        bool r1 = (o[9] > o[4]);
        float ocraw = fmaxf(o[4], o[9]);       // raw logit: ordering & >0.5 threshold preserved
        float x = sigf(r1 ? o[5] : o[0]);
        float y = sigf(r1 ? o[6] : o[1]);
        float w = sigf(r1 ? o[7] : o[2]) * 448.0f;
        float h = sigf(r1 ? o[8] : o[3]) * 448.0f;
        float cx = (x + (float)cj) * gw, cy = (y + (float)ci) * gw;
        pbox[tid]  = make_float4(cx - 0.5f * w, cy - 0.5f * h, cx + 0.5f * w, cy + 0.5f * h);
        pconf[tid] = ocraw;
        int bi = 0; float bv = o[10];
        #pragma unroll
        for (int c = 1; c < NCLS; c++) { float v = o[10 + c]; if (v > bv) { bv = v; bi = c; } }
        pcls[tid] = bi;

        // ground truth
        float tw = t[2] * 448.0f, th = t[3] * 448.0f;
        float gcx = (t[0] + (float)cj) * gw, gcy = (t[1] + (float)ci) * gw;
        gbox[tid] = make_float4(gcx - 0.5f * tw, gcy - 0.5f * th, gcx + 0.5f * tw, gcy + 0.5f * th);
        int gi = 0; float gv = t[10];
        #pragma unroll
        for (int c = 1; c < NCLS; c++) { float v = t[10 + c]; if (v > gv) { gv = v; gi = c; } }
        gcls[tid] = gi;
        unsigned char gvv = (t[4] > 0.5f) ? 1 : 0;
        gval[tid] = gvv;
        if (gvv) atomicAdd(&hist[gi], 1);
    }
    __syncthreads();

    // ---- stable descending sort by conf: rank = #{better} (tie -> lower index first) ----
    if (tid < NBOX) {
        float myc = pconf[tid];
        int r = 0;
        for (int j = 0; j < NBOX; j++) {
            float cj2 = pconf[j];
            if (cj2 > myc || (cj2 == myc && j < tid)) r++;
        }
        sbox[r] = pbox[tid]; sconf[r] = myc; scls[r] = pcls[tid];
    }
    __syncthreads();

    // ---- concurrently: warps 0-1 -> suppression masks (j>i only); warps 2-3 -> GT match ----
    if (tid < NBOX) {
        float4 b = sbox[tid];
        int kc = scls[tid];
        unsigned long long m = 0ULL;
        for (int j = tid + 1; j < NBOX; j++) {
            if (scls[j] == kc && iou(b, sbox[j]) > 0.5f) m |= (1ULL << j);
        }
        sup[tid] = m;
    } else if (tid >= 64 && tid < 64 + NBOX) {
        int i = tid - 64;
        float4 b = sbox[i];
        int kc = scls[i];
        float best = -1.0f; int bid = 0;
        for (int j = 0; j < NBOX; j++) {
            float v = -1.0f;
            if (gval[j] && gcls[j] == kc) v = iou(b, gbox[j]);
            if (v > best) { best = v; bid = j; }
        }
        smx[i] = best; sbest[i] = bid;
    }
    __syncthreads();

    // ---- sequential greedy NMS + greedy TP assignment + per-class bitmasks ----
    if (tid == 0) {
        unsigned long long suppressed = 0ULL, matched = 0ULL;
        for (int i = 0; i < NBOX; i++) {
            bool active = !((suppressed >> i) & 1ULL);
            if (active) suppressed |= sup[i];        // sup[i] already only has bits > i
            int c = scls[i];
            bool vp  = active && (sconf[i] > 0.0f);  // raw logit > 0 <=> sigmoid > 0.5
            bool hit = vp && (smx[i] > 0.5f) && !((matched >> sbest[i]) & 1ULL);
            if (hit) matched |= (1ULL << sbest[i]);
            unsigned long long bit = 1ULL << i;
            if (vp)  sActM[c] |= bit;
            if (hit) sTpM[c]  |= bit;
            sent[i] = (unsigned char)((vp ? 1 : 0) | (hit ? 2 : 0) | (c << 3));
        }
    }
    __syncthreads();

    if (tid < NBOX) g_entry[(size_t)img * NBOX + tid] = sent[tid];
    if (tid < NCLS) {
        unsigned long long am = sActM[tid], tm = sTpM[tid];
        g_actM[img][tid] = am;
        g_tpM[img][tid]  = tm;
        g_cnt[0][tid][img] = __popcll(am);
        g_cnt[1][tid][img] = __popcll(tm);
        int hv = hist[tid];
        if (hv) atomicAdd(&g_gt[tid], hv);
    }
}

// Parallel exclusive scan: one block per (word, class), 4096 values, 1024 thr x 4 elems
__global__ void k_scan() {
    __shared__ int wsum[32];
    int* base = &g_cnt[0][0][0] + (size_t)blockIdx.x * BSZ;
    int t = threadIdx.x, lane = t & 31, wid = t >> 5;

    int v0 = base[t * 4 + 0], v1 = base[t * 4 + 1];
    int v2 = base[t * 4 + 2], v3 = base[t * 4 + 3];
    int s = v0 + v1 + v2 + v3;

    int inc = s;
    #pragma unroll
    for (int o = 1; o < 32; o <<= 1) {
        int n = __shfl_up_sync(0xffffffffu, inc, o);
        if (lane >= o) inc += n;
    }
    if (lane == 31) wsum[wid] = inc;
    __syncthreads();
    if (wid == 0) {
        int wv = wsum[lane];
        int wi = wv;
        #pragma unroll
        for (int o = 1; o < 32; o <<= 1) {
            int n = __shfl_up_sync(0xffffffffu, wi, o);
            if (lane >= o) wi += n;
        }
        wsum[lane] = wi - wv;   // exclusive
    }
    __syncthreads();
    int ex = wsum[wid] + (inc - s);   // exclusive base for this thread's 4 elems
    base[t * 4 + 0] = ex;
    base[t * 4 + 1] = ex + v0;
    base[t * 4 + 2] = ex + v0 + v1;
    base[t * 4 + 3] = ex + v0 + v1 + v2;
}

// AP contributions: pure map over entries; local prefix via popc of per-class bitmasks
__global__ void k_ap() {
    int idx = blockIdx.x * blockDim.x + threadIdx.x;
    if (idx >= NE) return;
    unsigned char e = g_entry[idx];
    if ((e & 3) == 3) {
        int img = idx / NBOX;
        int t   = idx - img * NBOX;
        int c   = e >> 3;
        unsigned long long below = (1ULL << t) - 1ULL;
        int locA = __popcll(g_actM[img][c] & below);
        int locT = __popcll(g_tpM[img][c]  & below);
        int k  = g_cnt[0][c][img] + locA + 1;  // global rank among active of class c (1-based)
        int TP = g_cnt[1][c][img] + locT + 1;  // cumulative TP including self
        float G = (float)g_gt[c];
        float pk = (float)TP / ((float)k + 1e-6f);
        float pprev;
        if (k > 1) pprev = (float)(TP - 1) / ((float)(k - 1) + 1e-6f);
        else       pprev = (idx == 0) ? 1.0f : 0.0f;   // prepended p=1 only at flat idx 0
        float dr = 1.0f / (G + 1e-6f);
        atomicAdd(&g_ap[c], (double)(dr * 0.5f * (pk + pprev)));
    }
}

__global__ void k_final(float* __restrict__ out) {
    if (threadIdx.x == 0) {
        double s = 0.0; int nh = 0;
        for (int c = 0; c < NCLS; c++) {
            if (g_gt[c] > 0) { s += g_ap[c]; nh++; }
        }
        double n = (double)(nh > 0 ? nh : 1);
        out[0] = (float)(s / n);
    }
}

extern "C" void kernel_launch(void* const* d_in, const int* in_sizes, int n_in,
                              void* d_out, int out_size) {
    const float* tgt  = (const float*)d_in[0];   // target  [4096,7,7,30]
    const float* outp = (const float*)d_in[1];   // output  [4096,7,7,30]
    (void)in_sizes; (void)n_in; (void)out_size;

    k_reset<<<1, 32>>>();
    k_image<<<BSZ, 128>>>(tgt, outp);
    k_scan<<<2 * NCLS, 1024>>>();
    k_ap<<<(NE + 255) / 256, 256>>>();
    k_final<<<1, 32>>>((float*)d_out);
}

// round 11
// speedup vs baseline: 2.0551x; 1.4511x over previous
#include <cuda_runtime.h>
#include <math.h>

// Problem constants (fixed by the reference)
#define S      7
#define NBOX   49          // S*S
#define NCLS   20
#define DCH    30          // B*5+C
#define BSZ    4096

// Persistent device scratch (allocation-free rule)
__device__ int                g_cnt[3][NCLS][BSZ];  // rows 0/1: act/tp counts -> excl bases; row 2: GT hist
__device__ unsigned long long g_actM[BSZ][NCLS];    // per-image per-class valid-pred bitmask (sorted pos)
__device__ unsigned long long g_tpM[BSZ][NCLS];     // per-image per-class TP bitmask
__device__ int                g_gt[NCLS];           // GT count per class (written by k_scan)
__device__ double             g_ap[NCLS];           // AP accumulators (zeroed by k_scan)

__device__ __forceinline__ float sigf(float x) {
    return 1.0f / (1.0f + expf(-x));
}

// One block per image, 256 threads.
__global__ void k_image(const float* __restrict__ tgt, const float* __restrict__ outp) {
    const int img = blockIdx.x;
    const int tid = threadIdx.x;

    __shared__ float4 pbox[NBOX];  __shared__ float pconf[NBOX]; __shared__ int pcls[NBOX]; __shared__ float parea[NBOX];
    __shared__ float4 gbox[NBOX];  __shared__ float garea[NBOX]; __shared__ int gcl[NBOX];  // -1 = invalid GT
    __shared__ float4 sbox[NBOX];  __shared__ float sconf_[NBOX]; __shared__ int scls[NBOX]; __shared__ float sarea[NBOX];
    __shared__ unsigned long long sup2[2 * NBOX];
    __shared__ float bI2[2 * NBOX], bU2[2 * NBOX]; __shared__ int bid2[2 * NBOX];
    __shared__ unsigned long long sSup[NBOX];
    __shared__ unsigned char sHit[NBOX]; __shared__ int sBid[NBOX];
    __shared__ int hist[NCLS];
    __shared__ unsigned long long sActM[NCLS], sTpM[NCLS];

    if (tid < NCLS) { hist[tid] = 0; sActM[tid] = 0ULL; sTpM[tid] = 0ULL; }
    __syncthreads();

    // ---- decode: 49 threads, one cell each (2x 120B contiguous via float2) ----
    float myconf = -1.0f;
    if (tid < NBOX) {
        const int ci = tid / S, cj = tid % S;
        const float gw = 448.0f / (float)S;
        const float2* ob = (const float2*)(outp + (size_t)img * (S * S * DCH) + tid * DCH);
        const float2* tb = (const float2*)(tgt  + (size_t)img * (S * S * DCH) + tid * DCH);

        float2 p0 = ob[0], p1 = ob[1], p2 = ob[2], p3 = ob[3], p4 = ob[4];
        // class argmax folded into the load stream (sigmoid monotonic -> raw logits)
        int bi = 0; float bv;
        { float2 v = ob[5]; bv = v.x; if (v.y > bv) { bv = v.y; bi = 1; } }
        #pragma unroll
        for (int k = 6; k < 15; k++) {
            float2 v = ob[k]; int base = 2 * k - 10;
            if (v.x > bv) { bv = v.x; bi = base; }
            if (v.y > bv) { bv = v.y; bi = base + 1; }
        }
        float2 q0 = tb[0], q1 = tb[1], q2 = tb[2];
        int gi = 0; float gv;
        { float2 v = tb[5]; gv = v.x; if (v.y > gv) { gv = v.y; gi = 1; } }
        #pragma unroll
        for (int k = 6; k < 15; k++) {
            float2 v = tb[k]; int base = 2 * k - 10;
            if (v.x > gv) { gv = v.x; gi = base; }
            if (v.y > gv) { gv = v.y; gi = base + 1; }
        }

        float o4 = p2.x, o9 = p4.y;
        bool r1 = (o9 > o4);
        myconf = fmaxf(o4, o9);             // raw logit: ordering & >0.5 threshold preserved
        float x = sigf(r1 ? p2.y : p0.x);
        float y = sigf(r1 ? p3.x : p0.y);
        float w = sigf(r1 ? p3.y : p1.x) * 448.0f;
        float h = sigf(r1 ? p4.x : p1.y) * 448.0f;
        float cx = (x + (float)cj) * gw, cy = (y + (float)ci) * gw;
        pbox[tid]  = make_float4(cx - 0.5f * w, cy - 0.5f * h, cx + 0.5f * w, cy + 0.5f * h);
        pconf[tid] = myconf;
        pcls[tid]  = bi;
        parea[tid] = w * h;

        float tw = q1.x * 448.0f, th = q1.y * 448.0f;
        float gcx = (q0.x + (float)cj) * gw, gcy = (q0.y + (float)ci) * gw;
        gbox[tid]  = make_float4(gcx - 0.5f * tw, gcy - 0.5f * th, gcx + 0.5f * tw, gcy + 0.5f * th);
        garea[tid] = tw * th;
        bool gvv = (q2.x > 0.5f);
        gcl[tid] = gvv ? gi : -1;
        if (gvv) atomicAdd(&hist[gi], 1);
    }
    // barrier + count of conf>0.5 boxes (only those can be valid or suppress valid ones)
    const int m = __syncthreads_count(myconf > 0.0f);

    // ---- stable descending sort by conf: rank = #{better} (tie -> lower index first) ----
    if (tid < NBOX) {
        int r = 0;
        for (int j = 0; j < NBOX; j++) {
            float cj2 = pconf[j];
            if (cj2 > myconf || (cj2 == myconf && j < tid)) r++;
        }
        sbox[r] = pbox[tid]; sconf_[r] = myconf; scls[r] = pcls[tid]; sarea[r] = parea[tid];
    }
    __syncthreads();

    // ---- suppression rows (threads 0..97, 2 per row) | GT match rows (threads 128..225) ----
    if (tid < 2 * NBOX) {
        int r = tid >> 1, h = tid & 1;
        if (r < m) {
            float4 b = sbox[r]; int kc = scls[r]; float aa = sarea[r];
            int lo = r + 1, n = NBOX - lo;
            int j0 = lo + (h ? (n >> 1) : 0);
            int j1 = h ? NBOX : (lo + (n >> 1));
            unsigned long long mm = 0ULL;
            for (int j = j0; j < j1; j++) {
                if (scls[j] == kc) {
                    float4 c = sbox[j];
                    float lx = fmaxf(b.x, c.x), ly = fmaxf(b.y, c.y);
                    float rx = fminf(b.z, c.z), ry = fminf(b.w, c.w);
                    float iw = fmaxf(rx - lx, 0.0f), ih = fmaxf(ry - ly, 0.0f);
                    float inter = iw * ih;
                    // iou > 0.5  <=>  3*inter > areaA + areaB   (union > 0)
                    if (3.0f * inter > aa + sarea[j]) mm |= (1ULL << j);
                }
            }
            sup2[tid] = mm;
        }
    } else if (tid >= 128 && tid < 128 + 2 * NBOX) {
        int u = tid - 128, r = u >> 1, h = u & 1;
        if (r < m) {
            float4 b = sbox[r]; int kc = scls[r]; float aa = sarea[r];
            float bI = -1.0f, bU = 1.0f; int bb = 0;   // sentinel value -1
            int j0 = h ? 24 : 0, j1 = h ? NBOX : 24;
            for (int j = j0; j < j1; j++) {
                if (gcl[j] == kc) {
                    float4 g = gbox[j];
                    float lx = fmaxf(b.x, g.x), ly = fmaxf(b.y, g.y);
                    float rx = fminf(b.z, g.z), ry = fminf(b.w, g.w);
                    float iw = fmaxf(rx - lx, 0.0f), ih = fmaxf(ry - ly, 0.0f);
                    float inter = iw * ih;
                    float un = aa + garea[j] - inter;      // > 0 (pred area > 0)
                    if (inter * bU > bI * un) { bI = inter; bU = un; bb = j; }  // strict: first max kept
                }
            }
            bI2[u] = bI; bU2[u] = bU; bid2[u] = bb;
        }
    }
    __syncthreads();

    // ---- combine halves ----
    if (tid < m) {
        sSup[tid] = sup2[2 * tid] | sup2[2 * tid + 1];
        float bI0 = bI2[2 * tid], bU0 = bU2[2 * tid];
        float bI1 = bI2[2 * tid + 1], bU1 = bU2[2 * tid + 1];
        bool take1 = (bI1 * bU0 > bI0 * bU1);   // strict: ties -> half0 (lower GT indices)
        float bI = take1 ? bI1 : bI0, bU = take1 ? bU1 : bU0;
        sHit[tid] = (2.0f * bI > bU) ? 1 : 0;   // iou > 0.5
        sBid[tid] = take1 ? bid2[2 * tid + 1] : bid2[2 * tid];
    }
    __syncthreads();

    // ---- sequential greedy NMS + greedy TP assignment (m iters) ----
    if (tid == 0) {
        unsigned long long suppressed = 0ULL, matched = 0ULL;
        for (int i = 0; i < m; i++) {
            if (!((suppressed >> i) & 1ULL)) {
                suppressed |= sSup[i];                  // bits > i only
                int c = scls[i];
                unsigned long long bit = 1ULL << i;
                sActM[c] |= bit;                        // valid: active && conf>0.5 (i<m)
                if (sHit[i] && !((matched >> sBid[i]) & 1ULL)) {
                    matched |= (1ULL << sBid[i]);
                    sTpM[c] |= bit;
                }
            }
        }
    }
    __syncthreads();

    if (tid < NCLS) {
        unsigned long long am = sActM[tid], tm = sTpM[tid];
        g_actM[img][tid] = am;
        g_tpM[img][tid]  = tm;
        g_cnt[0][tid][img] = __popcll(am);
        g_cnt[1][tid][img] = __popcll(tm);
        g_cnt[2][tid][img] = hist[tid];
    }
}

// blocks 0..39: exclusive scan of rows 0/1 (4096 each, 1024 thr x 4)
// blocks 40..59: reduce row 2 -> g_gt[c]; zero g_ap[c]
__global__ void k_scan() {
    __shared__ int wsum[32];
    int t = threadIdx.x, lane = t & 31, wid = t >> 5;

    if (blockIdx.x < 2 * NCLS) {
        int* base = &g_cnt[0][0][0] + (size_t)blockIdx.x * BSZ;
        int v0 = base[t * 4 + 0], v1 = base[t * 4 + 1];
        int v2 = base[t * 4 + 2], v3 = base[t * 4 + 3];
        int s = v0 + v1 + v2 + v3;
        int inc = s;
        #pragma unroll
        for (int o = 1; o < 32; o <<= 1) {
            int n = __shfl_up_sync(0xffffffffu, inc, o);
            if (lane >= o) inc += n;
        }
        if (lane == 31) wsum[wid] = inc;
        __syncthreads();
        if (wid == 0) {
            int wv = wsum[lane];
            int wi = wv;
            #pragma unroll
            for (int o = 1; o < 32; o <<= 1) {
                int n = __shfl_up_sync(0xffffffffu, wi, o);
                if (lane >= o) wi += n;
            }
            wsum[lane] = wi - wv;   // exclusive
        }
        __syncthreads();
        int ex = wsum[wid] + (inc - s);
        base[t * 4 + 0] = ex;
        base[t * 4 + 1] = ex + v0;
        base[t * 4 + 2] = ex + v0 + v1;
        base[t * 4 + 3] = ex + v0 + v1 + v2;
    } else {
        int c = blockIdx.x - 2 * NCLS;
        const int* row = &g_cnt[2][c][0];
        int s = row[t] + row[t + 1024] + row[t + 2048] + row[t + 3072];
        #pragma unroll
        for (int o = 16; o > 0; o >>= 1) s += __shfl_down_sync(0xffffffffu, s, o);
        if (lane == 0) wsum[wid] = s;
        __syncthreads();
        if (t == 0) {
            int tot = 0;
            #pragma unroll
            for (int i = 0; i < 32; i++) tot += wsum[i];
            g_gt[c] = tot;
            g_ap[c] = 0.0;
        }
    }
}

// AP contributions: one thread per (image, class); iterate TP-mask bits
__global__ void k_ap() {
    int idx = blockIdx.x * blockDim.x + threadIdx.x;
    if (idx >= BSZ * NCLS) return;
    int img = idx / NCLS, c = idx - img * NCLS;
    unsigned long long tm0 = g_tpM[img][c];
    if (!tm0) return;
    unsigned long long am = g_actM[img][c];
    int baseA = g_cnt[0][c][img];
    int baseT = g_cnt[1][c][img];
    float G = (float)g_gt[c];
    float dr = 1.0f / (G + 1e-6f);
    double acc = 0.0;
    unsigned long long tm = tm0;
    while (tm) {
        int t = __ffsll((long long)tm) - 1;
        tm &= tm - 1;
        unsigned long long below = (1ULL << t) - 1ULL;
        int k  = baseA + __popcll(am  & below) + 1;  // global rank among active of class c
        int TP = baseT + __popcll(tm0 & below) + 1;  // cumulative TP including self
        float pk = (float)TP / ((float)k + 1e-6f);
        float pprev;
        if (k > 1) pprev = (float)(TP - 1) / ((float)(k - 1) + 1e-6f);
        else       pprev = (img == 0 && t == 0) ? 1.0f : 0.0f; // prepended p=1 only at flat idx 0
        acc += (double)(dr * 0.5f * (pk + pprev));
    }
    atomicAdd(&g_ap[c], acc);
}

__global__ void k_final(float* __restrict__ out) {
    if (threadIdx.x == 0) {
        double s = 0.0; int nh = 0;
        for (int c = 0; c < NCLS; c++) {
            if (g_gt[c] > 0) { s += g_ap[c]; nh++; }
        }
        double n = (double)(nh > 0 ? nh : 1);
        out[0] = (float)(s / n);
    }
}

extern "C" void kernel_launch(void* const* d_in, const int* in_sizes, int n_in,
                              void* d_out, int out_size) {
    const float* tgt  = (const float*)d_in[0];   // target  [4096,7,7,30]
    const float* outp = (const float*)d_in[1];   // output  [4096,7,7,30]
    (void)in_sizes; (void)n_in; (void)out_size;

    k_image<<<BSZ, 256>>>(tgt, outp);
    k_scan<<<3 * NCLS, 1024>>>();
    k_ap<<<(BSZ * NCLS + 255) / 256, 256>>>();
    k_final<<<1, 32>>>((float*)d_out);
}

// round 15
// speedup vs baseline: 2.0649x; 1.0048x over previous
#include <cuda_runtime.h>
#include <math.h>

#define S      7
#define NBOX   49
#define NCLS   20
#define DCH    30
#define BSZ    4096
#define WPB    8            // warps (=images) per block
#define FULLM  0xffffffffu

// Persistent device scratch (allocation-free rule)
__device__ unsigned long long g_actM[NCLS][BSZ];   // per-class per-image valid-pred bitmask (sorted pos)
__device__ unsigned long long g_tpM[NCLS][BSZ];    // per-class per-image TP bitmask
__device__ int                g_gth[NCLS][BSZ];    // per-class per-image GT count
__device__ int                g_gt[NCLS];          // total GT per class (written by k_cls)
__device__ double             g_ap[NCLS];          // per-class AP (written by k_cls)

__device__ __forceinline__ float sigf(float x) { return 1.0f / (1.0f + expf(-x)); }

// ---- k_image: one WARP per image, 8 images per 256-thread block ----
__global__ void k_image(const float* __restrict__ tgt, const float* __restrict__ outp) {
    const int lane = threadIdx.x & 31;
    const int wimg = threadIdx.x >> 5;
    const int img  = blockIdx.x * WPB + wimg;

    __shared__ float4 sbox[WPB][NBOX];  __shared__ int   scls[WPB][NBOX];  __shared__ float sarea[WPB][NBOX];
    __shared__ float4 gbox[WPB][NBOX];  __shared__ int   gcl[WPB][NBOX];   __shared__ float garea[WPB][NBOX];
    __shared__ unsigned long long sup[WPB][NBOX];
    __shared__ int   hitbid[WPB][NBOX];       // bid | (hit<<8)
    __shared__ int   hist[WPB][NCLS];

    if (lane < NCLS) hist[wimg][lane] = 0;
    __syncwarp();

    // ---- Phase A: decode 2 cells per lane (cells lane, lane+32) ----
    float  conf0 = -1e30f, conf1 = -1e30f;
    float4 box0, box1;
    float  area0 = 0.f, area1 = 0.f;
    int    cls0 = 0, cls1 = 0;
    const float gw = 448.0f / (float)S;

    #pragma unroll
    for (int half = 0; half < 2; half++) {
        int e = lane + half * 32;
        if (e < NBOX) {
            const int ci = e / S, cj = e % S;
            const float2* ob = (const float2*)(outp + (size_t)img * (S * S * DCH) + e * DCH);
            const float2* tb = (const float2*)(tgt  + (size_t)img * (S * S * DCH) + e * DCH);

            float2 p0 = ob[0], p1 = ob[1], p2 = ob[2], p3 = ob[3], p4 = ob[4];
            int bi = 0; float bv;
            { float2 v = ob[5]; bv = v.x; if (v.y > bv) { bv = v.y; bi = 1; } }
            #pragma unroll
            for (int k = 6; k < 15; k++) {
                float2 v = ob[k]; int base = 2 * k - 10;
                if (v.x > bv) { bv = v.x; bi = base; }
                if (v.y > bv) { bv = v.y; bi = base + 1; }
            }
            float2 q0 = tb[0], q1 = tb[1], q2 = tb[2];
            int gi = 0; float gv;
            { float2 v = tb[5]; gv = v.x; if (v.y > gv) { gv = v.y; gi = 1; } }
            #pragma unroll
            for (int k = 6; k < 15; k++) {
                float2 v = tb[k]; int base = 2 * k - 10;
                if (v.x > gv) { gv = v.x; gi = base; }
                if (v.y > gv) { gv = v.y; gi = base + 1; }
            }

            float o4 = p2.x, o9 = p4.y;
            bool r1 = (o9 > o4);
            float cf = fmaxf(o4, o9);            // raw logit: ordering & >0.5 preserved
            float x = sigf(r1 ? p2.y : p0.x);
            float y = sigf(r1 ? p3.x : p0.y);
            float w = sigf(r1 ? p3.y : p1.x) * 448.0f;
            float h = sigf(r1 ? p4.x : p1.y) * 448.0f;
            float cx = (x + (float)cj) * gw, cy = (y + (float)ci) * gw;
            float4 bx = make_float4(cx - 0.5f * w, cy - 0.5f * h, cx + 0.5f * w, cy + 0.5f * h);

            float tw = q1.x * 448.0f, th = q1.y * 448.0f;
            float gcx = (q0.x + (float)cj) * gw, gcy = (q0.y + (float)ci) * gw;
            gbox[wimg][e]  = make_float4(gcx - 0.5f * tw, gcy - 0.5f * th, gcx + 0.5f * tw, gcy + 0.5f * th);
            garea[wimg][e] = tw * th;
            bool gvv = (q2.x > 0.5f);
            gcl[wimg][e] = gvv ? gi : -1;
            if (gvv) atomicAdd(&hist[wimg][gi], 1);

            if (half == 0) { conf0 = cf; box0 = bx; area0 = w * h; cls0 = bi; }
            else           { conf1 = cf; box1 = bx; area1 = w * h; cls1 = bi; }
        }
    }

    // m = #boxes with conf>0.5 (raw logit > 0)
    unsigned b0 = __ballot_sync(FULLM, conf0 > 0.0f);
    unsigned b1 = __ballot_sync(FULLM, conf1 > 0.0f);
    const int m = __popc(b0) + __popc(b1);

    // ---- Phase B: stable conf-desc rank via broadcast shfl, then scatter ----
    int r0 = 0, r1c = 0;
    const int cell0 = lane, cell1 = lane + 32;
    for (int k = 0; k < NBOX; k++) {
        float ck = (k < 32) ? __shfl_sync(FULLM, conf0, k) : __shfl_sync(FULLM, conf1, k - 32);
        r0  += (ck > conf0) || (ck == conf0 && k < cell0);
        r1c += (ck > conf1) || (ck == conf1 && k < cell1);
    }
    sbox[wimg][r0] = box0; scls[wimg][r0] = cls0; sarea[wimg][r0] = area0;
    if (cell1 < NBOX) { sbox[wimg][r1c] = box1; scls[wimg][r1c] = cls1; sarea[wimg][r1c] = area1; }
    __syncwarp();

    // ---- Phase C: suppression (j>i) + best same-class GT, rows lane & lane+32 ----
    #pragma unroll
    for (int half = 0; half < 2; half++) {
        int r = lane + half * 32;
        if (r < m) {
            float4 b = sbox[wimg][r]; int kc = scls[wimg][r]; float aa = sarea[wimg][r];
            unsigned long long mm = 0ULL;
            for (int j = r + 1; j < NBOX; j++) {
                if (scls[wimg][j] == kc) {
                    float4 c = sbox[wimg][j];
                    float lx = fmaxf(b.x, c.x), ly = fmaxf(b.y, c.y);
                    float rx = fminf(b.z, c.z), ry = fminf(b.w, c.w);
                    float iw = fmaxf(rx - lx, 0.0f), ih = fmaxf(ry - ly, 0.0f);
                    // iou > 0.5  <=>  3*inter > areaA + areaB (union > 0)
                    if (3.0f * (iw * ih) > aa + sarea[wimg][j]) mm |= (1ULL << j);
                }
            }
            sup[wimg][r] = mm;

            float bI = -1.0f, bU = 1.0f; int bb = 0;
            for (int j = 0; j < NBOX; j++) {
                if (gcl[wimg][j] == kc) {
                    float4 g = gbox[wimg][j];
                    float lx = fmaxf(b.x, g.x), ly = fmaxf(b.y, g.y);
                    float rx = fminf(b.z, g.z), ry = fminf(b.w, g.w);
                    float iw = fmaxf(rx - lx, 0.0f), ih = fmaxf(ry - ly, 0.0f);
                    float inter = iw * ih;
                    float un = aa + garea[wimg][j] - inter;     // > 0 (pred area > 0)
                    if (inter * bU > bI * un) { bI = inter; bU = un; bb = j; }  // first max kept
                }
            }
            hitbid[wimg][r] = bb | ((2.0f * bI > bU) ? 0x100 : 0);   // iou > 0.5
        }
    }
    __syncwarp();

    // ---- Phase D: sequential greedy NMS + greedy TP match (lane 0) ----
    unsigned long long actM = 0ULL, tpM = 0ULL;
    if (lane == 0) {
        unsigned long long suppressed = 0ULL, matched = 0ULL;
        for (int i = 0; i < m; i++) {
            if (!((suppressed >> i) & 1ULL)) {
                suppressed |= sup[wimg][i];            // bits > i only
                unsigned long long bit = 1ULL << i;
                actM |= bit;                            // active && conf>0.5 (i<m)
                int hb = hitbid[wimg][i];
                int bd = hb & 0xff;
                if ((hb & 0x100) && !((matched >> bd) & 1ULL)) {
                    matched |= (1ULL << bd);
                    tpM |= bit;
                }
            }
        }
    }
    actM = __shfl_sync(FULLM, actM, 0);
    tpM  = __shfl_sync(FULLM, tpM, 0);

    // ---- Phase E: per-class masks + writeout (lanes 0..19) ----
    if (lane < NCLS) {
        unsigned long long amc = 0ULL, tmc = 0ULL;
        unsigned long long t = actM;
        while (t) {
            int i = __ffsll((long long)t) - 1;
            t &= t - 1;
            if (scls[wimg][i] == lane) {
                unsigned long long bit = 1ULL << i;
                amc |= bit;
                if ((tpM >> i) & 1ULL) tmc |= bit;
            }
        }
        g_actM[lane][img] = amc;
        g_tpM[lane][img]  = tmc;
        g_gth[lane][img]  = hist[wimg][lane];
    }
}

// ---- k_cls: one block per class. GT reduce -> scans -> AP contributions -> g_ap[c] ----
__global__ void k_cls() {
    const int c = blockIdx.x;
    const int t = threadIdx.x, lane = t & 31, wid = t >> 5;
    __shared__ int    wsum[32];
    __shared__ int    sG;
    __shared__ double wacc[32];

    // load 4 images per thread
    unsigned long long am[4], tm[4];
    int aA[4], aT[4], sA = 0, sT = 0, sGt = 0;
    #pragma unroll
    for (int i = 0; i < 4; i++) {
        int img = t * 4 + i;
        am[i] = g_actM[c][img];
        tm[i] = g_tpM[c][img];
        aA[i] = __popcll(am[i]);
        aT[i] = __popcll(tm[i]);
        sA += aA[i]; sT += aT[i];
        sGt += g_gth[c][img];
    }

    // GT total (block reduce)
    {
        int s = sGt;
        #pragma unroll
        for (int o = 16; o > 0; o >>= 1) s += __shfl_down_sync(FULLM, s, o);
        if (lane == 0) wsum[wid] = s;
        __syncthreads();
        if (t == 0) {
            int tot = 0;
            #pragma unroll
            for (int i = 0; i < 32; i++) tot += wsum[i];
            sG = tot; g_gt[c] = tot;
        }
        __syncthreads();
    }
    const float G = (float)sG;
    const float dr = 1.0f / (G + 1e-6f);

    // two exclusive block scans (act, tp) over thread sums
    int baseA, baseT;
    {
        int inc = sA;
        #pragma unroll
        for (int o = 1; o < 32; o <<= 1) { int n = __shfl_up_sync(FULLM, inc, o); if (lane >= o) inc += n; }
        if (lane == 31) wsum[wid] = inc;
        __syncthreads();
        if (wid == 0) {
            int wv = wsum[lane], wi = wv;
            #pragma unroll
            for (int o = 1; o < 32; o <<= 1) { int n = __shfl_up_sync(FULLM, wi, o); if (lane >= o) wi += n; }
            wsum[lane] = wi - wv;
        }
        __syncthreads();
        baseA = wsum[wid] + (inc - sA);
        __syncthreads();
        inc = sT;
        #pragma unroll
        for (int o = 1; o < 32; o <<= 1) { int n = __shfl_up_sync(FULLM, inc, o); if (lane >= o) inc += n; }
        if (lane == 31) wsum[wid] = inc;
        __syncthreads();
        if (wid == 0) {
            int wv = wsum[lane], wi = wv;
            #pragma unroll
            for (int o = 1; o < 32; o <<= 1) { int n = __shfl_up_sync(FULLM, wi, o); if (lane >= o) wi += n; }
            wsum[lane] = wi - wv;
        }
        __syncthreads();
        baseT = wsum[wid] + (inc - sT);
    }

    // AP contributions for this thread's 4 images
    double acc = 0.0;
    #pragma unroll
    for (int i = 0; i < 4; i++) {
        int img = t * 4 + i;
        unsigned long long tm0 = tm[i];
        unsigned long long tmr = tm0;
        while (tmr) {
            int p = __ffsll((long long)tmr) - 1;
            tmr &= tmr - 1;
            unsigned long long below = (1ULL << p) - 1ULL;
            int k  = baseA + __popcll(am[i] & below) + 1;
            int TP = baseT + __popcll(tm0   & below) + 1;
            float pk = (float)TP / ((float)k + 1e-6f);
            float pprev;
            if (k > 1) pprev = (float)(TP - 1) / ((float)(k - 1) + 1e-6f);
            else       pprev = (img == 0 && p == 0) ? 1.0f : 0.0f;  // prepended p=1 at flat idx 0
            acc += (double)(dr * 0.5f * (pk + pprev));
        }
        baseA += aA[i]; baseT += aT[i];
    }

    // block reduce doubles -> g_ap[c]
    #pragma unroll
    for (int o = 16; o > 0; o >>= 1) acc += __shfl_down_sync(FULLM, acc, o);
    if (lane == 0) wacc[wid] = acc;
    __syncthreads();
    if (t == 0) {
        double tot = 0.0;
        #pragma unroll
        for (int i = 0; i < 32; i++) tot += wacc[i];
        g_ap[c] = tot;
    }
}

// ---- k_final: 20 parallel lane loads + warp reduce ----
__global__ void k_final(float* __restrict__ out) {
    int lane = threadIdx.x;
    double ap = 0.0; int gt = 0;
    if (lane < NCLS) { ap = g_ap[lane]; gt = g_gt[lane]; }
    unsigned has = __ballot_sync(FULLM, gt > 0);
    double v = (gt > 0) ? ap : 0.0;
    #pragma unroll
    for (int o = 16; o > 0; o >>= 1) v += __shfl_down_sync(FULLM, v, o);
    if (lane == 0) {
        int nh = __popc(has);
        out[0] = (float)(v / (double)(nh > 0 ? nh : 1));
    }
}

extern "C" void kernel_launch(void* const* d_in, const int* in_sizes, int n_in,
                              void* d_out, int out_size) {
    const float* tgt  = (const float*)d_in[0];   // target  [4096,7,7,30]
    const float* outp = (const float*)d_in[1];   // output  [4096,7,7,30]
    (void)in_sizes; (void)n_in; (void)out_size;

    k_image<<<BSZ / WPB, 32 * WPB>>>(tgt, outp);
    k_cls<<<NCLS, 1024>>>();
    k_final<<<1, 32>>>((float*)d_out);
}

// round 17
// speedup vs baseline: 3.1576x; 1.5291x over previous
#include <cuda_runtime.h>
#include <math.h>

#define S      7
#define NBOX   49
#define NCLS   20
#define DCH    30
#define BSZ    4096
#define WPB    8            // warps (=images) per block
#define FULLM  0xffffffffu

// Persistent device scratch (allocation-free rule)
__device__ unsigned long long g_actM[NCLS][BSZ];   // per-class per-image valid-pred bitmask (sorted pos)
__device__ unsigned long long g_tpM[NCLS][BSZ];    // per-class per-image TP bitmask
__device__ int                g_gth[NCLS][BSZ];    // per-class per-image GT count
__device__ int                g_gt[NCLS];          // total GT per class (written by k_cls)
__device__ double             g_ap[NCLS];          // per-class AP (written by k_cls)

__device__ __forceinline__ float sigf(float x) { return 1.0f / (1.0f + expf(-x)); }

// ---- k_image: one WARP per image, 8 images per 256-thread block ----
__global__ void k_image(const float* __restrict__ tgt, const float* __restrict__ outp) {
    const int lane = threadIdx.x & 31;
    const int wimg = threadIdx.x >> 5;
    const int img  = blockIdx.x * WPB + wimg;

    __shared__ float4 sbox[WPB][NBOX];  __shared__ int scls[WPB][NBOX];  __shared__ float sarea[WPB][NBOX];
    __shared__ float4 gbox[WPB][NBOX];  __shared__ float garea[WPB][NBOX];
    __shared__ unsigned long long sup[WPB][NBOX];
    __shared__ int   hitbid[WPB][NBOX];                  // bid | (hit<<8)
    __shared__ unsigned long long classm[WPB][NCLS];     // sorted positions of class-c preds
    __shared__ unsigned long long gtm[WPB][NCLS];        // cells with valid class-c GT

    if (lane < NCLS) { classm[wimg][lane] = 0ULL; gtm[wimg][lane] = 0ULL; }
    __syncwarp();

    // ---- Phase A: decode 2 cells per lane (cells lane, lane+32) ----
    float  conf0 = -1e30f, conf1 = -1e30f;
    float4 box0, box1;
    float  area0 = 0.f, area1 = 0.f;
    int    cls0 = 0, cls1 = 0;
    const float gw = 448.0f / (float)S;

    #pragma unroll
    for (int half = 0; half < 2; half++) {
        int e = lane + half * 32;
        if (e < NBOX) {
            const int ci = e / S, cj = e % S;
            const float2* ob = (const float2*)(outp + (size_t)img * (S * S * DCH) + e * DCH);
            const float2* tb = (const float2*)(tgt  + (size_t)img * (S * S * DCH) + e * DCH);

            float2 p0 = ob[0], p1 = ob[1], p2 = ob[2], p3 = ob[3], p4 = ob[4];
            int bi = 0; float bv;
            { float2 v = ob[5]; bv = v.x; if (v.y > bv) { bv = v.y; bi = 1; } }
            #pragma unroll
            for (int k = 6; k < 15; k++) {
                float2 v = ob[k]; int base = 2 * k - 10;
                if (v.x > bv) { bv = v.x; bi = base; }
                if (v.y > bv) { bv = v.y; bi = base + 1; }
            }
            float2 q0 = tb[0], q1 = tb[1], q2 = tb[2];
            int gi = 0; float gv;
            { float2 v = tb[5]; gv = v.x; if (v.y > gv) { gv = v.y; gi = 1; } }
            #pragma unroll
            for (int k = 6; k < 15; k++) {
                float2 v = tb[k]; int base = 2 * k - 10;
                if (v.x > gv) { gv = v.x; gi = base; }
                if (v.y > gv) { gv = v.y; gi = base + 1; }
            }

            float o4 = p2.x, o9 = p4.y;
            bool r1 = (o9 > o4);
            float cf = fmaxf(o4, o9);            // raw logit: ordering & >0.5 preserved
            float x = sigf(r1 ? p2.y : p0.x);
            float y = sigf(r1 ? p3.x : p0.y);
            float w = sigf(r1 ? p3.y : p1.x) * 448.0f;
            float h = sigf(r1 ? p4.x : p1.y) * 448.0f;
            float cx = (x + (float)cj) * gw, cy = (y + (float)ci) * gw;
            float4 bx = make_float4(cx - 0.5f * w, cy - 0.5f * h, cx + 0.5f * w, cy + 0.5f * h);

            float tw = q1.x * 448.0f, th = q1.y * 448.0f;
            float gcx = (q0.x + (float)cj) * gw, gcy = (q0.y + (float)ci) * gw;
            gbox[wimg][e]  = make_float4(gcx - 0.5f * tw, gcy - 0.5f * th, gcx + 0.5f * tw, gcy + 0.5f * th);
            garea[wimg][e] = tw * th;
            if (q2.x > 0.5f) atomicOr(&gtm[wimg][gi], 1ULL << e);

            if (half == 0) { conf0 = cf; box0 = bx; area0 = w * h; cls0 = bi; }
            else           { conf1 = cf; box1 = bx; area1 = w * h; cls1 = bi; }
        }
    }

    // m = #boxes with conf>0.5 (raw logit > 0)
    unsigned bm0 = __ballot_sync(FULLM, conf0 > 0.0f);
    unsigned bm1 = __ballot_sync(FULLM, conf1 > 0.0f);
    const int m = __popc(bm0) + __popc(bm1);

    // ---- Phase B: stable conf-desc rank via broadcast shfl, scatter + class masks ----
    int r0 = 0, r1c = 0;
    const int cell0 = lane, cell1 = lane + 32;
    for (int k = 0; k < NBOX; k++) {
        float ck = (k < 32) ? __shfl_sync(FULLM, conf0, k) : __shfl_sync(FULLM, conf1, k - 32);
        r0  += (ck > conf0) || (ck == conf0 && k < cell0);
        r1c += (ck > conf1) || (ck == conf1 && k < cell1);
    }
    sbox[wimg][r0] = box0; scls[wimg][r0] = cls0; sarea[wimg][r0] = area0;
    atomicOr(&classm[wimg][cls0], 1ULL << r0);
    if (cell1 < NBOX) {
        sbox[wimg][r1c] = box1; scls[wimg][r1c] = cls1; sarea[wimg][r1c] = area1;
        atomicOr(&classm[wimg][cls1], 1ULL << r1c);
    }
    __syncwarp();

    // ---- Phase C: sparse suppression + sparse GT match (iterate class-mask bits only) ----
    #pragma unroll
    for (int half = 0; half < 2; half++) {
        int r = lane + half * 32;
        if (r < m) {
            float4 b = sbox[wimg][r]; int kc = scls[wimg][r]; float aa = sarea[wimg][r];

            unsigned long long cand = classm[wimg][kc] & ((~0ULL) << 1 << r);  // same-class, rank > r
            unsigned long long mm = 0ULL;
            while (cand) {
                int j = __ffsll((long long)cand) - 1;
                unsigned long long bit = cand & (~cand + 1ULL);
                cand &= cand - 1;
                float4 c = sbox[wimg][j];
                float lx = fmaxf(b.x, c.x), ly = fmaxf(b.y, c.y);
                float rx = fminf(b.z, c.z), ry = fminf(b.w, c.w);
                float iw = fmaxf(rx - lx, 0.0f), ih = fmaxf(ry - ly, 0.0f);
                // iou > 0.5  <=>  3*inter > areaA + areaB (union > 0)
                if (3.0f * (iw * ih) > aa + sarea[wimg][j]) mm |= bit;
            }
            sup[wimg][r] = mm;

            unsigned long long gc = gtm[wimg][kc];
            float bI = -1.0f, bU = 1.0f; int bb = 0;
            while (gc) {
                int j = __ffsll((long long)gc) - 1;
                gc &= gc - 1;
                float4 g = gbox[wimg][j];
                float lx = fmaxf(b.x, g.x), ly = fmaxf(b.y, g.y);
                float rx = fminf(b.z, g.z), ry = fminf(b.w, g.w);
                float iw = fmaxf(rx - lx, 0.0f), ih = fmaxf(ry - ly, 0.0f);
                float inter = iw * ih;
                float un = aa + garea[wimg][j] - inter;        // > 0 (pred area > 0)
                if (inter * bU > bI * un) { bI = inter; bU = un; bb = j; }  // first max kept
            }
            hitbid[wimg][r] = bb | ((2.0f * bI > bU) ? 0x100 : 0);   // iou > 0.5
        }
    }
    __syncwarp();

    // ---- Phase D: sequential greedy NMS + greedy TP match (lane 0) ----
    unsigned long long actM = 0ULL, tpM = 0ULL;
    if (lane == 0) {
        unsigned long long suppressed = 0ULL, matched = 0ULL;
        for (int i = 0; i < m; i++) {
            if (!((suppressed >> i) & 1ULL)) {
                suppressed |= sup[wimg][i];            // bits > i only
                unsigned long long bit = 1ULL << i;
                actM |= bit;                            // active && conf>0.5 (i<m)
                int hb = hitbid[wimg][i];
                int bd = hb & 0xff;
                if ((hb & 0x100) && !((matched >> bd) & 1ULL)) {
                    matched |= (1ULL << bd);
                    tpM |= bit;
                }
            }
        }
    }
    actM = __shfl_sync(FULLM, actM, 0);
    tpM  = __shfl_sync(FULLM, tpM, 0);

    // ---- Phase E: per-class masks are pure ANDs now ----
    if (lane < NCLS) {
        unsigned long long cm = classm[wimg][lane];
        g_actM[lane][img] = cm & actM;
        g_tpM[lane][img]  = cm & tpM;
        g_gth[lane][img]  = __popcll(gtm[wimg][lane]);
    }
}

// ---- k_cls: one block per class. GT reduce -> scans -> AP contributions -> g_ap[c] ----
__global__ void k_cls() {
    const int c = blockIdx.x;
    const int t = threadIdx.x, lane = t & 31, wid = t >> 5;
    __shared__ int    wsum[32];
    __shared__ int    sG;
    __shared__ double wacc[32];

    // load 4 images per thread
    unsigned long long am[4], tm[4];
    int aA[4], aT[4], sA = 0, sT = 0, sGt = 0;
    #pragma unroll
    for (int i = 0; i < 4; i++) {
        int img = t * 4 + i;
        am[i] = g_actM[c][img];
        tm[i] = g_tpM[c][img];
        aA[i] = __popcll(am[i]);
        aT[i] = __popcll(tm[i]);
        sA += aA[i]; sT += aT[i];
        sGt += g_gth[c][img];
    }

    // GT total (block reduce)
    {
        int s = sGt;
        #pragma unroll
        for (int o = 16; o > 0; o >>= 1) s += __shfl_down_sync(FULLM, s, o);
        if (lane == 0) wsum[wid] = s;
        __syncthreads();
        if (t == 0) {
            int tot = 0;
            #pragma unroll
            for (int i = 0; i < 32; i++) tot += wsum[i];
            sG = tot; g_gt[c] = tot;
        }
        __syncthreads();
    }
    const float G = (float)sG;
    const float dr = 1.0f / (G + 1e-6f);

    // two exclusive block scans (act, tp) over thread sums
    int baseA, baseT;
    {
        int inc = sA;
        #pragma unroll
        for (int o = 1; o < 32; o <<= 1) { int n = __shfl_up_sync(FULLM, inc, o); if (lane >= o) inc += n; }
        if (lane == 31) wsum[wid] = inc;
        __syncthreads();
        if (wid == 0) {
            int wv = wsum[lane], wi = wv;
            #pragma unroll
            for (int o = 1; o < 32; o <<= 1) { int n = __shfl_up_sync(FULLM, wi, o); if (lane >= o) wi += n; }
            wsum[lane] = wi - wv;
        }
        __syncthreads();
        baseA = wsum[wid] + (inc - sA);
        __syncthreads();
        inc = sT;
        #pragma unroll
        for (int o = 1; o < 32; o <<= 1) { int n = __shfl_up_sync(FULLM, inc, o); if (lane >= o) inc += n; }
        if (lane == 31) wsum[wid] = inc;
        __syncthreads();
        if (wid == 0) {
            int wv = wsum[lane], wi = wv;
            #pragma unroll
            for (int o = 1; o < 32; o <<= 1) { int n = __shfl_up_sync(FULLM, wi, o); if (lane >= o) wi += n; }
            wsum[lane] = wi - wv;
        }
        __syncthreads();
        baseT = wsum[wid] + (inc - sT);
    }

    // AP contributions for this thread's 4 images
    double acc = 0.0;
    #pragma unroll
    for (int i = 0; i < 4; i++) {
        int img = t * 4 + i;
        unsigned long long tm0 = tm[i];
        unsigned long long tmr = tm0;
        while (tmr) {
            int p = __ffsll((long long)tmr) - 1;
            tmr &= tmr - 1;
            unsigned long long below = (1ULL << p) - 1ULL;
            int k  = baseA + __popcll(am[i] & below) + 1;
            int TP = baseT + __popcll(tm0   & below) + 1;
            float pk = (float)TP / ((float)k + 1e-6f);
            float pprev;
            if (k > 1) pprev = (float)(TP - 1) / ((float)(k - 1) + 1e-6f);
            else       pprev = (img == 0 && p == 0) ? 1.0f : 0.0f;  // prepended p=1 at flat idx 0
            acc += (double)(dr * 0.5f * (pk + pprev));
        }
        baseA += aA[i]; baseT += aT[i];
    }

    // block reduce doubles -> g_ap[c]
    #pragma unroll
    for (int o = 16; o > 0; o >>= 1) acc += __shfl_down_sync(FULLM, acc, o);
    if (lane == 0) wacc[wid] = acc;
    __syncthreads();
    if (t == 0) {
        double tot = 0.0;
        #pragma unroll
        for (int i = 0; i < 32; i++) tot += wacc[i];
        g_ap[c] = tot;
    }
}

// ---- k_final: 20 parallel lane loads + warp reduce ----
__global__ void k_final(float* __restrict__ out) {
    int lane = threadIdx.x;
    double ap = 0.0; int gt = 0;
    if (lane < NCLS) { ap = g_ap[lane]; gt = g_gt[lane]; }
    unsigned has = __ballot_sync(FULLM, gt > 0);
    double v = (gt > 0) ? ap : 0.0;
    #pragma unroll
    for (int o = 16; o > 0; o >>= 1) v += __shfl_down_sync(FULLM, v, o);
    if (lane == 0) {
        int nh = __popc(has);
        out[0] = (float)(v / (double)(nh > 0 ? nh : 1));
    }
}

extern "C" void kernel_launch(void* const* d_in, const int* in_sizes, int n_in,
                              void* d_out, int out_size) {
    const float* tgt  = (const float*)d_in[0];   // target  [4096,7,7,30]
    const float* outp = (const float*)d_in[1];   // output  [4096,7,7,30]
    (void)in_sizes; (void)n_in; (void)out_size;

    k_image<<<BSZ / WPB, 32 * WPB>>>(tgt, outp);
    k_cls<<<NCLS, 1024>>>();
    k_final<<<1, 32>>>((float*)d_out);
}